// round 12
// baseline (speedup 1.0000x reference)
#include <cuda_runtime.h>
#include <cuda_bf16.h>
#include <cstdint>

// ---------------------------------------------------------------------------
// miScore: out[i,k] = (1/256) * sum_j sigmoid( y_a[i,:] . (W @ y_b[j,:] + b) )
//
// S0: convert y_b, W fp32 -> bf16 ; zero g_s, g_cnt (spare blocks)
// S1: proj = y_b @ W^T + b (HMMA, 128 CTAs) || convert y_a (128 CTAs)
// S2: PERSISTENT fused HMMA bf16 GEMM + tanh-sigmoid + atomic row sums;
//     the LAST CTA of each 128-row block writes the broadcast output.
//     304 CTAs (2/SM), tile 128x128, BK=32 chunks, 5-stage ring, depth-3
//     prefetch (loads issued BEFORE waits), one __syncthreads per chunk.
// ---------------------------------------------------------------------------

#define NUSR 8192
#define HDIM 256
#define NTILE 4096
#define PGRID 304

__device__ __align__(16) __nv_bfloat16 g_ya[NUSR * HDIM];     // 4 MB
__device__ __align__(16) __nv_bfloat16 g_yb[NUSR * HDIM];     // 4 MB
__device__ __align__(16) __nv_bfloat16 g_wb[HDIM * HDIM];     // 128 KB
__device__ __align__(16) __nv_bfloat16 g_projb[NUSR * HDIM];  // 4 MB
__device__ float g_s[NUSR];
__device__ unsigned g_cnt[64];

// ---------------- cp.async helpers ----------------
__device__ __forceinline__ void cp_async16(uint32_t dst, const void* src) {
    asm volatile("cp.async.cg.shared.global [%0], [%1], 16;" :: "r"(dst), "l"(src));
}
#define CP_COMMIT() asm volatile("cp.async.commit_group;" ::: "memory")
#define CP_WAIT3()  asm volatile("cp.async.wait_group 3;" ::: "memory")
#define CP_WAIT2()  asm volatile("cp.async.wait_group 2;" ::: "memory")
#define CP_WAIT1()  asm volatile("cp.async.wait_group 1;" ::: "memory")
#define CP_WAIT0()  asm volatile("cp.async.wait_group 0;" ::: "memory")

// ---------------- mma / ldmatrix ----------------
__device__ __forceinline__ void ldsm_x4(uint32_t* r, uint32_t addr) {
    asm volatile("ldmatrix.sync.aligned.m8n8.x4.shared.b16 {%0,%1,%2,%3}, [%4];"
                 : "=r"(r[0]), "=r"(r[1]), "=r"(r[2]), "=r"(r[3]) : "r"(addr));
}
__device__ __forceinline__ void mma16816(float* c, const uint32_t* a, const uint32_t* b) {
    asm volatile(
        "mma.sync.aligned.m16n8k16.row.col.f32.bf16.bf16.f32 "
        "{%0,%1,%2,%3}, {%4,%5,%6,%7}, {%8,%9}, {%0,%1,%2,%3};"
        : "+f"(c[0]), "+f"(c[1]), "+f"(c[2]), "+f"(c[3])
        : "r"(a[0]), "r"(a[1]), "r"(a[2]), "r"(a[3]), "r"(b[0]), "r"(b[1]));
}
__device__ __forceinline__ float fast_tanh(float x) {
    float t;
    asm("tanh.approx.f32 %0, %1;" : "=f"(t) : "f"(x));
    return t;
}

// ===========================================================================
// S0: convert y_b, W -> bf16 (blocks 0..2111); zero g_s, g_cnt (2112..2119).
// ===========================================================================
__global__ void convert_ybw_kernel(const float* __restrict__ yb,
                                   const float* __restrict__ W) {
    const int bx = blockIdx.x;
    if (bx >= 2112) {
        const int o = (bx - 2112) * 1024 + threadIdx.x * 4;
        *(float4*)&g_s[o] = make_float4(0.f, 0.f, 0.f, 0.f);
        if (bx == 2119 && threadIdx.x < 64) g_cnt[threadIdx.x] = 0u;
        return;
    }
    const int idx = bx * 256 + threadIdx.x;
    const float* src;
    __nv_bfloat162* dst;
    int off;
    if (idx < 524288) { src = yb; dst = (__nv_bfloat162*)g_yb; off = idx; }
    else              { src = W;  dst = (__nv_bfloat162*)g_wb; off = idx - 524288; }
    float4 v = ((const float4*)src)[off];
    dst[off * 2 + 0] = __floats2bfloat162_rn(v.x, v.y);
    dst[off * 2 + 1] = __floats2bfloat162_rn(v.z, v.w);
}

// ===========================================================================
// S1: blocks 0..127: proj = y_b @ W^T + b (HMMA, CTA 128x128)
//     blocks 128..255: convert y_a -> bf16
// ===========================================================================
#define PSROW 40
#define PA_BYTES (128 * PSROW * 2)
#define PBUF_BYTES (2 * PA_BYTES)

__global__ void __launch_bounds__(256, 1) proj_and_convert_kernel(
        const float* __restrict__ bias, const float* __restrict__ ya) {
    __shared__ __align__(16) char smem[2 * PBUF_BYTES];

    const int tid = threadIdx.x;
    const int bx = blockIdx.x;

    if (bx >= 128) {   // ---- y_a conversion blocks ----
        const int base = (bx - 128) * 4096;
        __nv_bfloat162* dst = (__nv_bfloat162*)g_ya;
        #pragma unroll
        for (int u = 0; u < 16; u++) {
            const int off = base + u * 256 + tid;
            float4 v = ((const float4*)ya)[off];
            dst[off * 2 + 0] = __floats2bfloat162_rn(v.x, v.y);
            dst[off * 2 + 1] = __floats2bfloat162_rn(v.z, v.w);
        }
        return;
    }

    // ---- proj blocks ----
    const uint32_t sbase = (uint32_t)__cvta_generic_to_shared(smem);
    const int wid = tid >> 5, lane = tid & 31;
    const int wm0 = (wid & 1) * 64;
    const int wn0 = (wid >> 1) * 32;
    const int j0 = (bx >> 1) * 128;
    const int s0 = (bx & 1) * 128;

    float acc[4][4][4];
    #pragma unroll
    for (int mt = 0; mt < 4; mt++)
        #pragma unroll
        for (int nt = 0; nt < 4; nt++)
            #pragma unroll
            for (int e = 0; e < 4; e++) acc[mt][nt][e] = 0.0f;

    auto load_chunk = [&](uint32_t dstb, int kt) {
        #pragma unroll
        for (int t = 0; t < 4; t++) {
            int g = tid + t * 256;
            if (g < 512) {
                int row = g >> 2, c = g & 3;
                cp_async16(dstb + (row * PSROW + c * 8) * 2,
                           g_yb + (size_t)(j0 + row) * HDIM + kt + c * 8);
            } else {
                int gb = g - 512;
                int row = gb >> 2, c = gb & 3;
                cp_async16(dstb + PA_BYTES + (row * PSROW + c * 8) * 2,
                           g_wb + (size_t)(s0 + row) * HDIM + kt + c * 8);
            }
        }
        CP_COMMIT();
    };

    load_chunk(sbase, 0);

    const int sub = lane >> 3, r8 = lane & 7;

    int buf = 0;
    #pragma unroll 1
    for (int it = 0; it < 8; it++) {
        if (it < 7) { load_chunk(sbase + (1 - buf) * PBUF_BYTES, (it + 1) * 32); CP_WAIT1(); }
        else        { CP_WAIT0(); }
        __syncthreads();

        const uint32_t aBase = sbase + buf * PBUF_BYTES;
        const uint32_t bBase = aBase + PA_BYTES;

        #pragma unroll
        for (int kk = 0; kk < 32; kk += 16) {
            uint32_t afrag[4][4];
            #pragma unroll
            for (int mt = 0; mt < 4; mt++) {
                int row = wm0 + mt * 16 + (sub & 1) * 8 + r8;
                int col = kk + (sub >> 1) * 8;
                ldsm_x4(afrag[mt], aBase + (row * PSROW + col) * 2);
            }
            uint32_t bfrag[4][2];
            #pragma unroll
            for (int p = 0; p < 2; p++) {
                int row = wn0 + p * 16 + (sub >> 1) * 8 + r8;
                int col = kk + (sub & 1) * 8;
                uint32_t t4[4];
                ldsm_x4(t4, bBase + (row * PSROW + col) * 2);
                bfrag[p * 2 + 0][0] = t4[0]; bfrag[p * 2 + 0][1] = t4[1];
                bfrag[p * 2 + 1][0] = t4[2]; bfrag[p * 2 + 1][1] = t4[3];
            }
            #pragma unroll
            for (int mt = 0; mt < 4; mt++)
                #pragma unroll
                for (int nt = 0; nt < 4; nt++)
                    mma16816(acc[mt][nt], afrag[mt], bfrag[nt]);
        }
        __syncthreads();
        buf ^= 1;
    }

    #pragma unroll
    for (int nt = 0; nt < 4; nt++) {
        const int gc = s0 + wn0 + nt * 8 + 2 * (lane & 3);
        const float b0 = bias[gc], b1 = bias[gc + 1];
        #pragma unroll
        for (int mt = 0; mt < 4; mt++) {
            const int rlo = j0 + wm0 + mt * 16 + (lane >> 2);
            *((__nv_bfloat162*)&g_projb[(size_t)rlo * HDIM + gc]) =
                __floats2bfloat162_rn(acc[mt][nt][0] + b0, acc[mt][nt][1] + b1);
            *((__nv_bfloat162*)&g_projb[(size_t)(rlo + 8) * HDIM + gc]) =
                __floats2bfloat162_rn(acc[mt][nt][2] + b0, acc[mt][nt][3] + b1);
        }
    }
}

// ===========================================================================
// S2: persistent fused HMMA bf16 GEMM + sigmoid + atomic row sums + output.
//   304 CTAs x 128 thr; tile 128x128; 4 warps 2(M)x2(N); warp tile 64x64.
//   Chunk = BK=32; 5-stage ring; depth-3 prefetch; 1 sync per chunk.
//   WAR safe: load(q+3) writes stage (q+3)%5, last read at chunk q-2;
//   every warp passed iteration q-1's barrier, which follows compute(q-2).
//   Tile epilogue: tanh-sigmoid, quad reduce, atomicAdd g_s; the 64th CTA
//   of each row-block broadcasts g_s/256 into out.
// ===========================================================================
#define SROWB 80                                     // 64 B data + 16 B pad
#define STG_A (128 * SROWB)                          // 10240
#define STG_BYTES (2 * STG_A)                        // 20480 (A + B)
#define NST 5
#define SV_OFF (NST * STG_BYTES)                     // 102400
#define FUSED_SMEM (SV_OFF + 128 * 4 + 16)           // 102928

__global__ void __launch_bounds__(128, 2) fused_hmma_persist(float* __restrict__ out) {
    extern __shared__ __align__(16) char smem[];
    const uint32_t sbase = (uint32_t)__cvta_generic_to_shared(smem);
    float* s_v = (float*)(smem + SV_OFF);            // [128] + flag
    unsigned* s_flag = (unsigned*)(smem + SV_OFF + 128 * 4);

    const int tid = threadIdx.x;
    const int wid = tid >> 5, lane = tid & 31;
    const int wm0 = (wid & 1) * 64;
    const int wn0 = (wid >> 1) * 64;
    const int sub = lane >> 3, r8 = lane & 7;
    const int bid = blockIdx.x;

    const int ntile = (NTILE - bid + PGRID - 1) / PGRID;
    const int G = ntile * 8;

    auto load_chunk = [&](int q) {
        const int tile = bid + (q >> 3) * PGRID;
        const int i0 = (tile >> 6) << 7;
        const int j0 = (tile & 63) << 7;
        const int kt = (q & 7) << 5;
        const uint32_t dstb = sbase + (q % NST) * STG_BYTES;
        #pragma unroll
        for (int t = 0; t < 8; t++) {
            int gg = tid + t * 128;
            if (gg < 512) {
                int row = gg >> 2, c = gg & 3;
                cp_async16(dstb + row * SROWB + c * 16,
                           g_ya + (size_t)(i0 + row) * HDIM + kt + c * 8);
            } else {
                int gb = gg - 512;
                int row = gb >> 2, c = gb & 3;
                cp_async16(dstb + STG_A + row * SROWB + c * 16,
                           g_projb + (size_t)(j0 + row) * HDIM + kt + c * 8);
            }
        }
        CP_COMMIT();
    };

    float acc[4][8][4];
    #pragma unroll
    for (int mt = 0; mt < 4; mt++)
        #pragma unroll
        for (int nt = 0; nt < 8; nt++)
            #pragma unroll
            for (int e = 0; e < 4; e++) acc[mt][nt][e] = 0.0f;

    load_chunk(0);
    load_chunk(1);
    load_chunk(2);

    #pragma unroll 1
    for (int q = 0; q < G; q++) {
        if (q + 3 < G) load_chunk(q + 3);            // issue BEFORE wait
        const int ahead = G - 1 - q;
        if (ahead >= 3)      { CP_WAIT3(); }
        else if (ahead == 2) { CP_WAIT2(); }
        else if (ahead == 1) { CP_WAIT1(); }
        else                 { CP_WAIT0(); }
        __syncthreads();                             // chunk q visible

        const uint32_t aBase = sbase + (q % NST) * STG_BYTES;
        const uint32_t bBase = aBase + STG_A;

        #pragma unroll
        for (int kk = 0; kk < 32; kk += 16) {
            uint32_t afrag[4][4];
            #pragma unroll
            for (int mt = 0; mt < 4; mt++) {
                int row = wm0 + mt * 16 + (sub & 1) * 8 + r8;
                int col = kk + (sub >> 1) * 8;
                ldsm_x4(afrag[mt], aBase + row * SROWB + col * 2);
            }
            uint32_t bfrag[8][2];
            #pragma unroll
            for (int p = 0; p < 4; p++) {
                int row = wn0 + p * 16 + (sub >> 1) * 8 + r8;
                int col = kk + (sub & 1) * 8;
                uint32_t t4[4];
                ldsm_x4(t4, bBase + row * SROWB + col * 2);
                bfrag[p * 2 + 0][0] = t4[0]; bfrag[p * 2 + 0][1] = t4[1];
                bfrag[p * 2 + 1][0] = t4[2]; bfrag[p * 2 + 1][1] = t4[3];
            }
            #pragma unroll
            for (int mt = 0; mt < 4; mt++)
                #pragma unroll
                for (int nt = 0; nt < 8; nt++)
                    mma16816(acc[mt][nt], afrag[mt], bfrag[nt]);
        }

        // ---- tile epilogue ----
        if ((q & 7) == 7) {
            const int tile = bid + (q >> 3) * PGRID;
            const int i0 = (tile >> 6) << 7;
            const int ib = tile >> 6;

            float rs[4][2];
            #pragma unroll
            for (int mt = 0; mt < 4; mt++) { rs[mt][0] = 0.0f; rs[mt][1] = 0.0f; }
            #pragma unroll
            for (int mt = 0; mt < 4; mt++)
                #pragma unroll
                for (int nt = 0; nt < 8; nt++) {
                    rs[mt][0] += 0.5f * fast_tanh(0.5f * acc[mt][nt][0])
                               + 0.5f * fast_tanh(0.5f * acc[mt][nt][1]);
                    rs[mt][1] += 0.5f * fast_tanh(0.5f * acc[mt][nt][2])
                               + 0.5f * fast_tanh(0.5f * acc[mt][nt][3]);
                }
            #pragma unroll
            for (int mt = 0; mt < 4; mt++)
                #pragma unroll
                for (int h = 0; h < 2; h++) {
                    rs[mt][h] += __shfl_xor_sync(0xffffffffu, rs[mt][h], 1);
                    rs[mt][h] += __shfl_xor_sync(0xffffffffu, rs[mt][h], 2);
                }
            if ((lane & 3) == 0) {
                const int rq = lane >> 2;
                #pragma unroll
                for (int mt = 0; mt < 4; mt++) {
                    atomicAdd(&g_s[i0 + wm0 + mt * 16 + 0 + rq], rs[mt][0] + 32.0f);
                    atomicAdd(&g_s[i0 + wm0 + mt * 16 + 8 + rq], rs[mt][1] + 32.0f);
                }
            }
            __threadfence();
            __syncthreads();
            if (tid == 0) *s_flag = (atomicAdd(&g_cnt[ib], 1u) == 63u) ? 1u : 0u;
            __syncthreads();
            if (*s_flag) {
                // last CTA of this row-block: broadcast g_s/256 to out
                __threadfence();
                if (tid < 128) {
                    volatile float* gs = g_s;
                    s_v[tid] = gs[i0 + tid] * (1.0f / 256.0f);
                }
                __syncthreads();
                #pragma unroll 1
                for (int k = tid; k < 8192; k += 128) {   // 128 rows x 64 f4
                    const int row = k >> 6, col = k & 63;
                    const float v = s_v[row];
                    ((float4*)(out + (size_t)(i0 + row) * HDIM))[col] =
                        make_float4(v, v, v, v);
                }
            }
            #pragma unroll
            for (int mt = 0; mt < 4; mt++)
                #pragma unroll
                for (int nt = 0; nt < 8; nt++)
                    #pragma unroll
                    for (int e = 0; e < 4; e++) acc[mt][nt][e] = 0.0f;
        }
    }
}

// ===========================================================================
extern "C" void kernel_launch(void* const* d_in, const int* in_sizes, int n_in,
                              void* d_out, int out_size) {
    const float* y_a = (const float*)d_in[0];
    const float* y_b = (const float*)d_in[1];
    const float* W   = (const float*)d_in[2];
    const float* b   = (const float*)d_in[3];
    float* out = (float*)d_out;

    cudaFuncSetAttribute(fused_hmma_persist,
                         cudaFuncAttributeMaxDynamicSharedMemorySize, FUSED_SMEM);

    convert_ybw_kernel<<<2120, 256>>>(y_b, W);
    proj_and_convert_kernel<<<256, 256>>>(b, y_a);
    fused_hmma_persist<<<PGRID, 128, FUSED_SMEM>>>(out);
}

// round 13
// speedup vs baseline: 1.4339x; 1.4339x over previous
#include <cuda_runtime.h>
#include <cuda_bf16.h>
#include <cstdint>

// ---------------------------------------------------------------------------
// miScore: out[i,k] = (1/256) * sum_j sigmoid( y_a[i,:] . (W @ y_b[j,:] + b) )
//
// Two launches:
// K1: blocks 0..127  : proj = y_b @ W^T + b  (reads fp32 directly,
//                      LDG->cvt->STS reg pipeline, HMMA bf16/f32, bf16 store)
//     blocks 128..255: convert y_a -> bf16 ; zero g_s / g_cnt
// K2: fused HMMA bf16 GEMM (f32 acc) + tanh-sigmoid + atomic row sums;
//     the 64th finishing CTA of each 128-row block writes the output.
//     CTA 128x128, 4 warps (64x64 warp tile), BK=64 x 4 chunks, 3-stage ring,
//     one __syncthreads per chunk, 2 CTAs/SM.
// ---------------------------------------------------------------------------

#define NUSR 8192
#define HDIM 256

__device__ __align__(16) __nv_bfloat16 g_ya[NUSR * HDIM];     // 4 MB
__device__ __align__(16) __nv_bfloat16 g_projb[NUSR * HDIM];  // 4 MB
__device__ float g_s[NUSR];
__device__ unsigned g_cnt[64];

// ---------------- cp.async helpers ----------------
__device__ __forceinline__ void cp_async16(uint32_t dst, const void* src) {
    asm volatile("cp.async.cg.shared.global [%0], [%1], 16;" :: "r"(dst), "l"(src));
}
#define CP_COMMIT() asm volatile("cp.async.commit_group;" ::: "memory")
#define CP_WAIT1()  asm volatile("cp.async.wait_group 1;" ::: "memory")
#define CP_WAIT0()  asm volatile("cp.async.wait_group 0;" ::: "memory")

// ---------------- mma / ldmatrix ----------------
__device__ __forceinline__ void ldsm_x4(uint32_t* r, uint32_t addr) {
    asm volatile("ldmatrix.sync.aligned.m8n8.x4.shared.b16 {%0,%1,%2,%3}, [%4];"
                 : "=r"(r[0]), "=r"(r[1]), "=r"(r[2]), "=r"(r[3]) : "r"(addr));
}
__device__ __forceinline__ void mma16816(float* c, const uint32_t* a, const uint32_t* b) {
    asm volatile(
        "mma.sync.aligned.m16n8k16.row.col.f32.bf16.bf16.f32 "
        "{%0,%1,%2,%3}, {%4,%5,%6,%7}, {%8,%9}, {%0,%1,%2,%3};"
        : "+f"(c[0]), "+f"(c[1]), "+f"(c[2]), "+f"(c[3])
        : "r"(a[0]), "r"(a[1]), "r"(a[2]), "r"(a[3]), "r"(b[0]), "r"(b[1]));
}
__device__ __forceinline__ float fast_tanh(float x) {
    float t;
    asm("tanh.approx.f32 %0, %1;" : "=f"(t) : "f"(x));
    return t;
}
__device__ __forceinline__ uint32_t bf2x2(float a, float b) {
    __nv_bfloat162 h = __floats2bfloat162_rn(a, b);
    return *(uint32_t*)&h;
}

// ===========================================================================
// K1: proj (fp32 sources) || y_a convert + zero scratch.
// ===========================================================================
#define PSROW 40                         // bf16 elems per smem row (80 B)
#define PA_BYTES (128 * PSROW * 2)       // 10240 per matrix per chunk

__global__ void __launch_bounds__(256, 1) proj_and_convert_kernel(
        const float* __restrict__ bias, const float* __restrict__ ya,
        const float* __restrict__ yb, const float* __restrict__ W) {
    __shared__ __align__(16) char smem[2 * PA_BYTES];

    const int tid = threadIdx.x;
    const int bx = blockIdx.x;

    if (bx >= 128) {   // ---- y_a conversion + scratch zeroing ----
        const int base = (bx - 128) * 4096;
        __nv_bfloat162* dst = (__nv_bfloat162*)g_ya;
        #pragma unroll
        for (int u = 0; u < 16; u++) {
            const int off = base + u * 256 + tid;
            float4 v = ((const float4*)ya)[off];
            dst[off * 2 + 0] = __floats2bfloat162_rn(v.x, v.y);
            dst[off * 2 + 1] = __floats2bfloat162_rn(v.z, v.w);
        }
        if (tid < 16) {
            const int o = (bx - 128) * 64 + tid * 4;
            *(float4*)&g_s[o] = make_float4(0.f, 0.f, 0.f, 0.f);
        }
        if (bx == 128 && tid < 64) g_cnt[tid] = 0u;
        return;
    }

    // ---- proj: CTA 128(Mj) x 128(Ns), K=256 as 8 BK=32 chunks ----
    const uint32_t sbase = (uint32_t)__cvta_generic_to_shared(smem);
    const int wid = tid >> 5, lane = tid & 31;
    const int wm0 = (wid & 1) * 64;
    const int wn0 = (wid >> 1) * 32;
    const int j0 = (bx >> 1) * 128;
    const int s0 = (bx & 1) * 128;

    // per-thread load slots: 2 granules (16B bf16 each) per matrix
    const int r0g = tid >> 2,          c0g = tid & 3;          // granule 0
    const int r1g = (tid + 256) >> 2,  c1g = (tid + 256) & 3;  // granule 1

    float acc[4][4][4];
    #pragma unroll
    for (int mt = 0; mt < 4; mt++)
        #pragma unroll
        for (int nt = 0; nt < 4; nt++)
            #pragma unroll
            for (int e = 0; e < 4; e++) acc[mt][nt][e] = 0.0f;

    // register-pipelined fp32 loads (8 float4 per thread per chunk)
    float4 rA[2][2], rB[2][2];
    auto ldg_chunk = [&](int kt, float4 (*A)[2], float4 (*B)[2]) {
        const float* a0 = yb + (size_t)(j0 + r0g) * HDIM + kt + c0g * 8;
        const float* a1 = yb + (size_t)(j0 + r1g) * HDIM + kt + c1g * 8;
        const float* b0 = W  + (size_t)(s0 + r0g) * HDIM + kt + c0g * 8;
        const float* b1 = W  + (size_t)(s0 + r1g) * HDIM + kt + c1g * 8;
        A[0][0] = *(const float4*)a0; A[0][1] = *(const float4*)(a0 + 4);
        A[1][0] = *(const float4*)a1; A[1][1] = *(const float4*)(a1 + 4);
        B[0][0] = *(const float4*)b0; B[0][1] = *(const float4*)(b0 + 4);
        B[1][0] = *(const float4*)b1; B[1][1] = *(const float4*)(b1 + 4);
    };
    auto sts_chunk = [&](float4 (*A)[2], float4 (*B)[2]) {
        #pragma unroll
        for (int t = 0; t < 2; t++) {
            const int row = t == 0 ? r0g : r1g;
            const int c16 = t == 0 ? c0g : c1g;
            const uint32_t off = (row * PSROW + c16 * 8) * 2;
            uint4 va, vb;
            va.x = bf2x2(A[t][0].x, A[t][0].y); va.y = bf2x2(A[t][0].z, A[t][0].w);
            va.z = bf2x2(A[t][1].x, A[t][1].y); va.w = bf2x2(A[t][1].z, A[t][1].w);
            vb.x = bf2x2(B[t][0].x, B[t][0].y); vb.y = bf2x2(B[t][0].z, B[t][0].w);
            vb.z = bf2x2(B[t][1].x, B[t][1].y); vb.w = bf2x2(B[t][1].z, B[t][1].w);
            asm volatile("st.shared.v4.b32 [%0], {%1,%2,%3,%4};"
                         :: "r"(sbase + off), "r"(va.x), "r"(va.y), "r"(va.z), "r"(va.w));
            asm volatile("st.shared.v4.b32 [%0], {%1,%2,%3,%4};"
                         :: "r"(sbase + PA_BYTES + off),
                            "r"(vb.x), "r"(vb.y), "r"(vb.z), "r"(vb.w));
        }
    };

    ldg_chunk(0, rA, rB);

    const int sub = lane >> 3, r8 = lane & 7;

    float4 nA[2][2], nB[2][2];
    #pragma unroll 1
    for (int it = 0; it < 8; it++) {
        __syncthreads();                  // prior chunk's smem reads complete
        sts_chunk(rA, rB);
        if (it < 7) ldg_chunk((it + 1) * 32, nA, nB);   // hide under compute
        __syncthreads();                  // chunk visible

        #pragma unroll
        for (int kk = 0; kk < 32; kk += 16) {
            uint32_t afrag[4][4];
            #pragma unroll
            for (int mt = 0; mt < 4; mt++) {
                int row = wm0 + mt * 16 + (sub & 1) * 8 + r8;
                int col = kk + (sub >> 1) * 8;
                ldsm_x4(afrag[mt], sbase + (row * PSROW + col) * 2);
            }
            uint32_t bfrag[4][2];
            #pragma unroll
            for (int p = 0; p < 2; p++) {
                int row = wn0 + p * 16 + (sub >> 1) * 8 + r8;
                int col = kk + (sub & 1) * 8;
                uint32_t t4[4];
                ldsm_x4(t4, sbase + PA_BYTES + (row * PSROW + col) * 2);
                bfrag[p * 2 + 0][0] = t4[0]; bfrag[p * 2 + 0][1] = t4[1];
                bfrag[p * 2 + 1][0] = t4[2]; bfrag[p * 2 + 1][1] = t4[3];
            }
            #pragma unroll
            for (int mt = 0; mt < 4; mt++)
                #pragma unroll
                for (int nt = 0; nt < 4; nt++)
                    mma16816(acc[mt][nt], afrag[mt], bfrag[nt]);
        }
        #pragma unroll
        for (int t = 0; t < 2; t++) {
            rA[t][0] = nA[t][0]; rA[t][1] = nA[t][1];
            rB[t][0] = nB[t][0]; rB[t][1] = nB[t][1];
        }
    }

    #pragma unroll
    for (int nt = 0; nt < 4; nt++) {
        const int gc = s0 + wn0 + nt * 8 + 2 * (lane & 3);
        const float b0 = bias[gc], b1 = bias[gc + 1];
        #pragma unroll
        for (int mt = 0; mt < 4; mt++) {
            const int rlo = j0 + wm0 + mt * 16 + (lane >> 2);
            *((__nv_bfloat162*)&g_projb[(size_t)rlo * HDIM + gc]) =
                __floats2bfloat162_rn(acc[mt][nt][0] + b0, acc[mt][nt][1] + b1);
            *((__nv_bfloat162*)&g_projb[(size_t)(rlo + 8) * HDIM + gc]) =
                __floats2bfloat162_rn(acc[mt][nt][2] + b0, acc[mt][nt][3] + b1);
        }
    }
}

// ===========================================================================
// K2: fused HMMA bf16 GEMM (f32 acc) + sigmoid + atomic row sums + output.
//   Grid (64 j-blocks, 64 i-blocks). CTA 128x128; 4 warps 2(M)x2(N).
//   K=256 as 4 BK=64 chunks, 3-stage ring, ONE sync per chunk. 2 CTAs/SM.
//   Last CTA per i-block (g_cnt) broadcasts g_s/256 into out.
// ===========================================================================
#define SROWB 144                                   // bytes per smem row
#define STG_A (128 * SROWB)                         // 18432
#define STG_BYTES (2 * STG_A)                       // 36864 (A + B)
#define NST 3
#define SV_OFF (NST * STG_BYTES)                    // 110592
#define FUSED_SMEM (SV_OFF + 128 * 4 + 16)          // 111120

__global__ void __launch_bounds__(128, 2) fused_hmma_kernel(float* __restrict__ out) {
    extern __shared__ __align__(16) char smem[];
    const uint32_t sbase = (uint32_t)__cvta_generic_to_shared(smem);
    float* s_v = (float*)(smem + SV_OFF);
    unsigned* s_flag = (unsigned*)(smem + SV_OFF + 128 * 4);

    const int tid = threadIdx.x;
    const int wid = tid >> 5, lane = tid & 31;
    const int wm0 = (wid & 1) * 64;
    const int wn0 = (wid >> 1) * 64;
    const int sub = lane >> 3, r8 = lane & 7;
    const int i0 = blockIdx.y * 128;
    const int j0 = blockIdx.x * 128;

    float acc[4][8][4];
    #pragma unroll
    for (int mt = 0; mt < 4; mt++)
        #pragma unroll
        for (int nt = 0; nt < 8; nt++)
            #pragma unroll
            for (int e = 0; e < 4; e++) acc[mt][nt][e] = 0.0f;

    auto load_chunk = [&](int g) {
        const uint32_t dstb = sbase + (g % NST) * STG_BYTES;
        const int kt = g * 64;
        #pragma unroll
        for (int t = 0; t < 16; t++) {
            int gg = tid + t * 128;
            if (gg < 1024) {
                int row = gg >> 3, c = gg & 7;
                cp_async16(dstb + row * SROWB + c * 16,
                           g_ya + (size_t)(i0 + row) * HDIM + kt + c * 8);
            } else {
                int gb = gg - 1024;
                int row = gb >> 3, c = gb & 7;
                cp_async16(dstb + STG_A + row * SROWB + c * 16,
                           g_projb + (size_t)(j0 + row) * HDIM + kt + c * 8);
            }
        }
        CP_COMMIT();
    };

    load_chunk(0);

    #pragma unroll 1
    for (int g = 0; g < 4; g++) {
        if (g < 3) { load_chunk(g + 1); CP_WAIT1(); }
        else       { CP_WAIT0(); }
        __syncthreads();

        const uint32_t aBase = sbase + (g % NST) * STG_BYTES;
        const uint32_t bBase = aBase + STG_A;

        #pragma unroll
        for (int kk = 0; kk < 64; kk += 16) {
            uint32_t afrag[4][4];
            #pragma unroll
            for (int mt = 0; mt < 4; mt++) {
                int row = wm0 + mt * 16 + (sub & 1) * 8 + r8;
                int col = kk + (sub >> 1) * 8;
                ldsm_x4(afrag[mt], aBase + row * SROWB + col * 2);
            }
            uint32_t bfrag[8][2];
            #pragma unroll
            for (int p = 0; p < 4; p++) {
                int row = wn0 + p * 16 + (sub >> 1) * 8 + r8;
                int col = kk + (sub & 1) * 8;
                uint32_t t4[4];
                ldsm_x4(t4, bBase + row * SROWB + col * 2);
                bfrag[p * 2 + 0][0] = t4[0]; bfrag[p * 2 + 0][1] = t4[1];
                bfrag[p * 2 + 1][0] = t4[2]; bfrag[p * 2 + 1][1] = t4[3];
            }
            #pragma unroll
            for (int mt = 0; mt < 4; mt++)
                #pragma unroll
                for (int nt = 0; nt < 8; nt++)
                    mma16816(acc[mt][nt], afrag[mt], bfrag[nt]);
        }
    }

    // ---- epilogue: sigmoid(x) = 0.5*tanh(x/2) + 0.5 ; atomic row sums ----
    float rs[4][2];
    #pragma unroll
    for (int mt = 0; mt < 4; mt++) { rs[mt][0] = 0.0f; rs[mt][1] = 0.0f; }
    #pragma unroll
    for (int mt = 0; mt < 4; mt++)
        #pragma unroll
        for (int nt = 0; nt < 8; nt++) {
            rs[mt][0] += 0.5f * fast_tanh(0.5f * acc[mt][nt][0])
                       + 0.5f * fast_tanh(0.5f * acc[mt][nt][1]);
            rs[mt][1] += 0.5f * fast_tanh(0.5f * acc[mt][nt][2])
                       + 0.5f * fast_tanh(0.5f * acc[mt][nt][3]);
        }
    #pragma unroll
    for (int mt = 0; mt < 4; mt++)
        #pragma unroll
        for (int h = 0; h < 2; h++) {
            rs[mt][h] += __shfl_xor_sync(0xffffffffu, rs[mt][h], 1);
            rs[mt][h] += __shfl_xor_sync(0xffffffffu, rs[mt][h], 2);
        }
    if ((lane & 3) == 0) {
        const int rq = lane >> 2;
        #pragma unroll
        for (int mt = 0; mt < 4; mt++) {
            atomicAdd(&g_s[i0 + wm0 + mt * 16 + 0 + rq], rs[mt][0] + 32.0f);
            atomicAdd(&g_s[i0 + wm0 + mt * 16 + 8 + rq], rs[mt][1] + 32.0f);
        }
    }

    // ---- completion counting; 64th CTA of this i-block writes output ----
    __threadfence();
    __syncthreads();
    if (tid == 0) *s_flag = (atomicAdd(&g_cnt[blockIdx.y], 1u) == 63u) ? 1u : 0u;
    __syncthreads();
    if (*s_flag) {
        __threadfence();
        volatile float* gs = g_s;
        s_v[tid] = gs[i0 + tid] * (1.0f / 256.0f);
        __syncthreads();
        #pragma unroll 1
        for (int k = tid; k < 8192; k += 128) {      // 128 rows x 64 float4
            const int row = k >> 6, col = k & 63;
            const float v = s_v[row];
            ((float4*)(out + (size_t)(i0 + row) * HDIM))[col] =
                make_float4(v, v, v, v);
        }
    }
}

// ===========================================================================
extern "C" void kernel_launch(void* const* d_in, const int* in_sizes, int n_in,
                              void* d_out, int out_size) {
    const float* y_a = (const float*)d_in[0];
    const float* y_b = (const float*)d_in[1];
    const float* W   = (const float*)d_in[2];
    const float* b   = (const float*)d_in[3];
    float* out = (float*)d_out;

    cudaFuncSetAttribute(fused_hmma_kernel,
                         cudaFuncAttributeMaxDynamicSharedMemorySize, FUSED_SMEM);

    proj_and_convert_kernel<<<256, 256>>>(b, y_a, y_b, W);
    fused_hmma_kernel<<<dim3(64, 64), 128, FUSED_SMEM>>>(out);
}

// round 14
// speedup vs baseline: 1.6049x; 1.1192x over previous
#include <cuda_runtime.h>
#include <cuda_bf16.h>
#include <cstdint>

// ---------------------------------------------------------------------------
// miScore: out[i,k] = (1/256) * sum_j sigmoid( y_a[i,:] . (W @ y_b[j,:] + b) )
//
// K1: blocks 0..127  : proj = y_b @ W^T + b (fp32 LDG -> bf16 STS pipeline)
//     blocks 128..255: convert y_a -> bf16 ; zero g_s
// K2: fused HMMA bf16 GEMM (f32 acc) + tanh-sigmoid + atomic row sums
//     CTA 128x128, 256 thr / 8 warps (4M x 2N, warp tile 32x64 -> 64 acc
//     regs), BK=64 x 4 chunks, 3-stage ring, 1 sync per chunk, 2 CTAs/SM
//     => 16 warps/SM to feed the tensor pipe (ncu showed 51.6% busy @ 8).
// K3: broadcast g_s/256 to out
// ---------------------------------------------------------------------------

#define NUSR 8192
#define HDIM 256

__device__ __align__(16) __nv_bfloat16 g_ya[NUSR * HDIM];     // 4 MB
__device__ __align__(16) __nv_bfloat16 g_projb[NUSR * HDIM];  // 4 MB
__device__ float g_s[NUSR];

// ---------------- cp.async helpers ----------------
__device__ __forceinline__ void cp_async16(uint32_t dst, const void* src) {
    asm volatile("cp.async.cg.shared.global [%0], [%1], 16;" :: "r"(dst), "l"(src));
}
#define CP_COMMIT() asm volatile("cp.async.commit_group;" ::: "memory")
#define CP_WAIT1()  asm volatile("cp.async.wait_group 1;" ::: "memory")
#define CP_WAIT0()  asm volatile("cp.async.wait_group 0;" ::: "memory")

// ---------------- mma / ldmatrix ----------------
__device__ __forceinline__ void ldsm_x4(uint32_t* r, uint32_t addr) {
    asm volatile("ldmatrix.sync.aligned.m8n8.x4.shared.b16 {%0,%1,%2,%3}, [%4];"
                 : "=r"(r[0]), "=r"(r[1]), "=r"(r[2]), "=r"(r[3]) : "r"(addr));
}
__device__ __forceinline__ void mma16816(float* c, const uint32_t* a, const uint32_t* b) {
    asm volatile(
        "mma.sync.aligned.m16n8k16.row.col.f32.bf16.bf16.f32 "
        "{%0,%1,%2,%3}, {%4,%5,%6,%7}, {%8,%9}, {%0,%1,%2,%3};"
        : "+f"(c[0]), "+f"(c[1]), "+f"(c[2]), "+f"(c[3])
        : "r"(a[0]), "r"(a[1]), "r"(a[2]), "r"(a[3]), "r"(b[0]), "r"(b[1]));
}
__device__ __forceinline__ float fast_tanh(float x) {
    float t;
    asm("tanh.approx.f32 %0, %1;" : "=f"(t) : "f"(x));
    return t;
}
__device__ __forceinline__ uint32_t bf2x2(float a, float b) {
    __nv_bfloat162 h = __floats2bfloat162_rn(a, b);
    return *(uint32_t*)&h;
}

// ===========================================================================
// K1: proj (fp32 sources) || y_a convert + zero g_s.   (unchanged from R13)
// ===========================================================================
#define PSROW 40
#define PA_BYTES (128 * PSROW * 2)

__global__ void __launch_bounds__(256, 1) proj_and_convert_kernel(
        const float* __restrict__ bias, const float* __restrict__ ya,
        const float* __restrict__ yb, const float* __restrict__ W) {
    __shared__ __align__(16) char smem[2 * PA_BYTES];

    const int tid = threadIdx.x;
    const int bx = blockIdx.x;

    if (bx >= 128) {   // ---- y_a conversion + g_s zeroing ----
        const int base = (bx - 128) * 4096;
        __nv_bfloat162* dst = (__nv_bfloat162*)g_ya;
        #pragma unroll
        for (int u = 0; u < 16; u++) {
            const int off = base + u * 256 + tid;
            float4 v = ((const float4*)ya)[off];
            dst[off * 2 + 0] = __floats2bfloat162_rn(v.x, v.y);
            dst[off * 2 + 1] = __floats2bfloat162_rn(v.z, v.w);
        }
        if (tid < 16) {
            const int o = (bx - 128) * 64 + tid * 4;
            *(float4*)&g_s[o] = make_float4(0.f, 0.f, 0.f, 0.f);
        }
        return;
    }

    // ---- proj: CTA 128(Mj) x 128(Ns), K=256 as 8 BK=32 chunks ----
    const uint32_t sbase = (uint32_t)__cvta_generic_to_shared(smem);
    const int wid = tid >> 5, lane = tid & 31;
    const int wm0 = (wid & 1) * 64;
    const int wn0 = (wid >> 1) * 32;
    const int j0 = (bx >> 1) * 128;
    const int s0 = (bx & 1) * 128;

    const int r0g = tid >> 2,          c0g = tid & 3;
    const int r1g = (tid + 256) >> 2,  c1g = (tid + 256) & 3;

    float acc[4][4][4];
    #pragma unroll
    for (int mt = 0; mt < 4; mt++)
        #pragma unroll
        for (int nt = 0; nt < 4; nt++)
            #pragma unroll
            for (int e = 0; e < 4; e++) acc[mt][nt][e] = 0.0f;

    float4 rA[2][2], rB[2][2];
    auto ldg_chunk = [&](int kt, float4 (*A)[2], float4 (*B)[2]) {
        const float* a0 = yb + (size_t)(j0 + r0g) * HDIM + kt + c0g * 8;
        const float* a1 = yb + (size_t)(j0 + r1g) * HDIM + kt + c1g * 8;
        const float* b0 = W  + (size_t)(s0 + r0g) * HDIM + kt + c0g * 8;
        const float* b1 = W  + (size_t)(s0 + r1g) * HDIM + kt + c1g * 8;
        A[0][0] = *(const float4*)a0; A[0][1] = *(const float4*)(a0 + 4);
        A[1][0] = *(const float4*)a1; A[1][1] = *(const float4*)(a1 + 4);
        B[0][0] = *(const float4*)b0; B[0][1] = *(const float4*)(b0 + 4);
        B[1][0] = *(const float4*)b1; B[1][1] = *(const float4*)(b1 + 4);
    };
    auto sts_chunk = [&](float4 (*A)[2], float4 (*B)[2]) {
        #pragma unroll
        for (int t = 0; t < 2; t++) {
            const int row = t == 0 ? r0g : r1g;
            const int c16 = t == 0 ? c0g : c1g;
            const uint32_t off = (row * PSROW + c16 * 8) * 2;
            uint4 va, vb;
            va.x = bf2x2(A[t][0].x, A[t][0].y); va.y = bf2x2(A[t][0].z, A[t][0].w);
            va.z = bf2x2(A[t][1].x, A[t][1].y); va.w = bf2x2(A[t][1].z, A[t][1].w);
            vb.x = bf2x2(B[t][0].x, B[t][0].y); vb.y = bf2x2(B[t][0].z, B[t][0].w);
            vb.z = bf2x2(B[t][1].x, B[t][1].y); vb.w = bf2x2(B[t][1].z, B[t][1].w);
            asm volatile("st.shared.v4.b32 [%0], {%1,%2,%3,%4};"
                         :: "r"(sbase + off), "r"(va.x), "r"(va.y), "r"(va.z), "r"(va.w));
            asm volatile("st.shared.v4.b32 [%0], {%1,%2,%3,%4};"
                         :: "r"(sbase + PA_BYTES + off),
                            "r"(vb.x), "r"(vb.y), "r"(vb.z), "r"(vb.w));
        }
    };

    ldg_chunk(0, rA, rB);

    const int sub = lane >> 3, r8 = lane & 7;

    float4 nA[2][2], nB[2][2];
    #pragma unroll 1
    for (int it = 0; it < 8; it++) {
        __syncthreads();
        sts_chunk(rA, rB);
        if (it < 7) ldg_chunk((it + 1) * 32, nA, nB);
        __syncthreads();

        #pragma unroll
        for (int kk = 0; kk < 32; kk += 16) {
            uint32_t afrag[4][4];
            #pragma unroll
            for (int mt = 0; mt < 4; mt++) {
                int row = wm0 + mt * 16 + (sub & 1) * 8 + r8;
                int col = kk + (sub >> 1) * 8;
                ldsm_x4(afrag[mt], sbase + (row * PSROW + col) * 2);
            }
            uint32_t bfrag[4][2];
            #pragma unroll
            for (int p = 0; p < 2; p++) {
                int row = wn0 + p * 16 + (sub >> 1) * 8 + r8;
                int col = kk + (sub & 1) * 8;
                uint32_t t4[4];
                ldsm_x4(t4, sbase + PA_BYTES + (row * PSROW + col) * 2);
                bfrag[p * 2 + 0][0] = t4[0]; bfrag[p * 2 + 0][1] = t4[1];
                bfrag[p * 2 + 1][0] = t4[2]; bfrag[p * 2 + 1][1] = t4[3];
            }
            #pragma unroll
            for (int mt = 0; mt < 4; mt++)
                #pragma unroll
                for (int nt = 0; nt < 4; nt++)
                    mma16816(acc[mt][nt], afrag[mt], bfrag[nt]);
        }
        #pragma unroll
        for (int t = 0; t < 2; t++) {
            rA[t][0] = nA[t][0]; rA[t][1] = nA[t][1];
            rB[t][0] = nB[t][0]; rB[t][1] = nB[t][1];
        }
    }

    #pragma unroll
    for (int nt = 0; nt < 4; nt++) {
        const int gc = s0 + wn0 + nt * 8 + 2 * (lane & 3);
        const float b0 = bias[gc], b1 = bias[gc + 1];
        #pragma unroll
        for (int mt = 0; mt < 4; mt++) {
            const int rlo = j0 + wm0 + mt * 16 + (lane >> 2);
            *((__nv_bfloat162*)&g_projb[(size_t)rlo * HDIM + gc]) =
                __floats2bfloat162_rn(acc[mt][nt][0] + b0, acc[mt][nt][1] + b1);
            *((__nv_bfloat162*)&g_projb[(size_t)(rlo + 8) * HDIM + gc]) =
                __floats2bfloat162_rn(acc[mt][nt][2] + b0, acc[mt][nt][3] + b1);
        }
    }
}

// ===========================================================================
// K2: fused HMMA bf16 GEMM (f32 acc) + sigmoid + atomic row sums.
//   CTA 128(M=i) x 128(N=j), 256 threads, 8 warps as 4(M) x 2(N),
//   warp tile 32x64 -> acc[2][8][4] = 64 regs. 2 CTAs/SM = 16 warps/SM.
//   K=256 as 4 BK=64 chunks, 3-stage ring, ONE sync per chunk.
// ===========================================================================
#define SROWB 144
#define STG_A (128 * SROWB)                         // 18432
#define STG_BYTES (2 * STG_A)                       // 36864
#define NST 3
#define FUSED_SMEM (NST * STG_BYTES)                // 110592

__global__ void __launch_bounds__(256, 2) fused_hmma_kernel() {
    extern __shared__ __align__(16) char smem[];
    const uint32_t sbase = (uint32_t)__cvta_generic_to_shared(smem);

    const int tid = threadIdx.x;
    const int wid = tid >> 5, lane = tid & 31;
    const int wm0 = (wid & 3) * 32;                 // 4 M-warps
    const int wn0 = (wid >> 2) * 64;                // 2 N-warps
    const int sub = lane >> 3, r8 = lane & 7;
    const int i0 = blockIdx.y * 128;
    const int j0 = blockIdx.x * 128;

    float acc[2][8][4];
    #pragma unroll
    for (int mt = 0; mt < 2; mt++)
        #pragma unroll
        for (int nt = 0; nt < 8; nt++)
            #pragma unroll
            for (int e = 0; e < 4; e++) acc[mt][nt][e] = 0.0f;

    // loader: A 1024 + B 1024 granules of 16 B; 8 per thread
    auto load_chunk = [&](int g) {
        const uint32_t dstb = sbase + (g % NST) * STG_BYTES;
        const int kt = g * 64;
        #pragma unroll
        for (int t = 0; t < 8; t++) {
            int gg = tid + t * 256;
            if (gg < 1024) {
                int row = gg >> 3, c = gg & 7;
                cp_async16(dstb + row * SROWB + c * 16,
                           g_ya + (size_t)(i0 + row) * HDIM + kt + c * 8);
            } else {
                int gb = gg - 1024;
                int row = gb >> 3, c = gb & 7;
                cp_async16(dstb + STG_A + row * SROWB + c * 16,
                           g_projb + (size_t)(j0 + row) * HDIM + kt + c * 8);
            }
        }
        CP_COMMIT();
    };

    load_chunk(0);

    #pragma unroll 1
    for (int g = 0; g < 4; g++) {
        if (g < 3) { load_chunk(g + 1); CP_WAIT1(); }
        else       { CP_WAIT0(); }
        __syncthreads();

        const uint32_t aBase = sbase + (g % NST) * STG_BYTES;
        const uint32_t bBase = aBase + STG_A;

        #pragma unroll
        for (int kk = 0; kk < 64; kk += 16) {
            uint32_t afrag[2][4];
            #pragma unroll
            for (int mt = 0; mt < 2; mt++) {
                int row = wm0 + mt * 16 + (sub & 1) * 8 + r8;
                int col = kk + (sub >> 1) * 8;
                ldsm_x4(afrag[mt], aBase + row * SROWB + col * 2);
            }
            uint32_t bfrag[8][2];
            #pragma unroll
            for (int p = 0; p < 4; p++) {
                int row = wn0 + p * 16 + (sub >> 1) * 8 + r8;
                int col = kk + (sub & 1) * 8;
                uint32_t t4[4];
                ldsm_x4(t4, bBase + row * SROWB + col * 2);
                bfrag[p * 2 + 0][0] = t4[0]; bfrag[p * 2 + 0][1] = t4[1];
                bfrag[p * 2 + 1][0] = t4[2]; bfrag[p * 2 + 1][1] = t4[3];
            }
            #pragma unroll
            for (int mt = 0; mt < 2; mt++)
                #pragma unroll
                for (int nt = 0; nt < 8; nt++)
                    mma16816(acc[mt][nt], afrag[mt], bfrag[nt]);
        }
    }

    // ---- epilogue: sigmoid(x) = 0.5*tanh(x/2) + 0.5 ; atomic row sums ----
    float rs[2][2];
    #pragma unroll
    for (int mt = 0; mt < 2; mt++) { rs[mt][0] = 0.0f; rs[mt][1] = 0.0f; }
    #pragma unroll
    for (int mt = 0; mt < 2; mt++)
        #pragma unroll
        for (int nt = 0; nt < 8; nt++) {
            rs[mt][0] += 0.5f * fast_tanh(0.5f * acc[mt][nt][0])
                       + 0.5f * fast_tanh(0.5f * acc[mt][nt][1]);
            rs[mt][1] += 0.5f * fast_tanh(0.5f * acc[mt][nt][2])
                       + 0.5f * fast_tanh(0.5f * acc[mt][nt][3]);
        }
    #pragma unroll
    for (int mt = 0; mt < 2; mt++)
        #pragma unroll
        for (int h = 0; h < 2; h++) {
            rs[mt][h] += __shfl_xor_sync(0xffffffffu, rs[mt][h], 1);
            rs[mt][h] += __shfl_xor_sync(0xffffffffu, rs[mt][h], 2);
        }
    if ((lane & 3) == 0) {
        const int rq = lane >> 2;
        // each rs bucket covers 64 columns -> add 64 * 0.5 = 32 constant
        #pragma unroll
        for (int mt = 0; mt < 2; mt++) {
            atomicAdd(&g_s[i0 + wm0 + mt * 16 + 0 + rq], rs[mt][0] + 32.0f);
            atomicAdd(&g_s[i0 + wm0 + mt * 16 + 8 + rq], rs[mt][1] + 32.0f);
        }
    }
}

// ===========================================================================
// K3: broadcast g_s/256 to out. One warp per output row.
// ===========================================================================
__global__ void bcast_kernel(float* __restrict__ out) {
    const int wid = threadIdx.x >> 5, lane = threadIdx.x & 31;
    const int row = blockIdx.x * 8 + wid;
    const float v = g_s[row] * (1.0f / 256.0f);
    float4* dst = (float4*)(out + (size_t)row * HDIM);
    const float4 vv = make_float4(v, v, v, v);
    dst[lane]      = vv;
    dst[lane + 32] = vv;
}

// ===========================================================================
extern "C" void kernel_launch(void* const* d_in, const int* in_sizes, int n_in,
                              void* d_out, int out_size) {
    const float* y_a = (const float*)d_in[0];
    const float* y_b = (const float*)d_in[1];
    const float* W   = (const float*)d_in[2];
    const float* b   = (const float*)d_in[3];
    float* out = (float*)d_out;

    cudaFuncSetAttribute(fused_hmma_kernel,
                         cudaFuncAttributeMaxDynamicSharedMemorySize, FUSED_SMEM);

    proj_and_convert_kernel<<<256, 256>>>(b, y_a, y_b, W);
    fused_hmma_kernel<<<dim3(64, 64), 256, FUSED_SMEM>>>();
    bcast_kernel<<<NUSR / 8, 256>>>(out);
}